// round 1
// baseline (speedup 1.0000x reference)
#include <cuda_runtime.h>
#include <math.h>
#include <float.h>

#define Hh   1024
#define Ww   1024
#define CSc  62      // (1024-900)/2
#define OFFc 72      // MS + CS
#define TWc  880     // template window
#define Sc   21      // 2*MS+1
#define MSc  10
#define EPSc 1e-8f

#define NA 220       // kernel A blocks (880 rows / 4)
#define ND 242       // kernel D blocks (22 row tiles * 11 col tiles)

// ---------------- scratch (no allocation allowed) ----------------
__device__ float g_ta[NA], g_tq[NA];          // template partial sums / sumsq
__device__ float g_colx[21 * 900];            // column sliding sums of Xc
__device__ float g_colq[21 * 900];            // column sliding sums of Xc^2
__device__ float g_ls[441], g_lq[441];        // window sums / sumsq per lag
__device__ float g_corr[ND * 441];            // per-block correlation partials
__device__ float g_xy[2];                     // xs, ys

// ---------------- helpers ----------------
__device__ __forceinline__ void blockReduce2(float& s, float& q, float* sh) {
    int lane = threadIdx.x & 31, w = threadIdx.x >> 5;
    for (int o = 16; o > 0; o >>= 1) {
        s += __shfl_down_sync(0xffffffffu, s, o);
        q += __shfl_down_sync(0xffffffffu, q, o);
    }
    if (lane == 0) { sh[w] = s; sh[32 + w] = q; }
    __syncthreads();
    int nw = (blockDim.x + 31) >> 5;
    if (w == 0) {
        s = (lane < nw) ? sh[lane] : 0.f;
        q = (lane < nw) ? sh[32 + lane] : 0.f;
        for (int o = 16; o > 0; o >>= 1) {
            s += __shfl_down_sync(0xffffffffu, s, o);
            q += __shfl_down_sync(0xffffffffu, q, o);
        }
    }
}

// ---------------- A: template sum / sumsq over [72:952]^2 ----------------
__global__ void kA(const float* __restrict__ T) {
    __shared__ float sh[64];
    int b = blockIdx.x, tid = threadIdx.x;
    float s = 0.f, q = 0.f;
    for (int rr = 0; rr < 4; rr++) {
        const float* row = T + (size_t)(OFFc + b * 4 + rr) * Ww + OFFc;
        for (int v = tid; v < TWc; v += 256) {
            float t = row[v]; s += t; q += t * t;
        }
    }
    blockReduce2(s, q, sh);
    if (tid == 0) { g_ta[b] = s; g_tq[b] = q; }
}

// ---------------- B: 880-tall column sliding sums over Xc (900x900) -------
__global__ void kB(const float* __restrict__ X) {
    int c = blockIdx.x * 256 + threadIdx.x;
    if (c >= 900) return;
    const float* p = X + (size_t)CSc * Ww + CSc + c;
    float s = 0.f, q = 0.f;
    for (int r = 0; r < TWc; r++) { float v = p[(size_t)r * Ww]; s += v; q += v * v; }
    g_colx[c] = s; g_colq[c] = q;
    for (int i = 1; i < Sc; i++) {
        float va = p[(size_t)(i + TWc - 1) * Ww];
        float vb = p[(size_t)(i - 1) * Ww];
        s += va - vb;
        q += va * va - vb * vb;
        g_colx[i * 900 + c] = s; g_colq[i * 900 + c] = q;
    }
}

// ---------------- C: 880-wide row sums of colwin -> ls, lsq per lag -------
__global__ void kC() {
    __shared__ float sh[64];
    int b = blockIdx.x;                // b = i*21 + j
    int i = b / 21, j = b % 21;
    int tid = threadIdx.x;
    float s = 0.f, q = 0.f;
    const float* px = g_colx + i * 900 + j;
    const float* pq = g_colq + i * 900 + j;
    for (int t = tid; t < TWc; t += 128) { s += px[t]; q += pq[t]; }
    blockReduce2(s, q, sh);
    if (tid == 0) { g_ls[b] = s; g_lq[b] = q; }
}

// ---------------- D: raw correlation, tiled + register blocked -----------
__global__ void __launch_bounds__(192) kD(const float* __restrict__ X,
                                          const float* __restrict__ T) {
    __shared__ float Xs[60 * 105];   // pitch 105 (== 9 mod 32): conflict-free
    __shared__ float Ts[40 * 81];    // pitch 81  (== 17 mod 32)
    int b = blockIdx.x;
    int bi = b / 11, bj = b % 11;    // 22 x 11 tiles of 40 x 80
    int bu0 = bi * 40, bv0 = bj * 80;
    int tid = threadIdx.x;

    const float* xg = X + (size_t)(CSc + bu0) * Ww + (CSc + bv0);
    for (int k = tid; k < 60 * 100; k += 192) {
        int ur = k / 100, uc = k - ur * 100;
        Xs[ur * 105 + uc] = xg[(size_t)ur * Ww + uc];
    }
    const float* tg = T + (size_t)(OFFc + bu0) * Ww + (OFFc + bv0);
    for (int k = tid; k < 40 * 80; k += 192) {
        int u = k / 80, v = k - u * 80;
        Ts[u * 81 + v] = tg[(size_t)u * Ww + v];
    }
    __syncthreads();

    int i = tid >> 3; if (i > 20) i = 20;   // clamp: threads 168..191 redundant
    int r = tid & 7;

    float acc[21];
#pragma unroll
    for (int j = 0; j < 21; j++) acc[j] = 0.f;

    for (int uu = 0; uu < 5; uu++) {        // tile rows r, r+8, ..., r+32
        int urow = r + uu * 8;
        const float* ts = Ts + urow * 81;
        const float* xs = Xs + (i + urow) * 105;
        for (int ch = 0; ch < 5; ch++) {    // 5 chunks of 16 columns
            float xw[36];
#pragma unroll
            for (int m = 0; m < 36; m++) xw[m] = xs[ch * 16 + m];
#pragma unroll
            for (int dv = 0; dv < 16; dv++) {
                float t = ts[ch * 16 + dv];
#pragma unroll
                for (int j = 0; j < 21; j++)
                    acc[j] = fmaf(t, xw[dv + j], acc[j]);
            }
        }
    }

#pragma unroll
    for (int j = 0; j < 21; j++) {
        float v = acc[j];
        v += __shfl_down_sync(0xffffffffu, v, 4, 8);
        v += __shfl_down_sync(0xffffffffu, v, 2, 8);
        v += __shfl_down_sync(0xffffffffu, v, 1, 8);
        if (r == 0 && tid < 168)
            g_corr[b * 441 + i * 21 + j] = v;
    }
}

// ---------------- E: reduce, NCC, argmax, subpixel ----------------
__global__ void __launch_bounds__(512) kE(float* __restrict__ out, int out_size) {
    __shared__ float sh[64];
    __shared__ float s_mT, s_tvar;
    __shared__ float s_ncc[441];
    __shared__ float rv[512];
    __shared__ int   ridx[512];
    int tid = threadIdx.x;

    // template stats
    float s = (tid < NA) ? g_ta[tid] : 0.f;
    float q = (tid < NA) ? g_tq[tid] : 0.f;
    blockReduce2(s, q, sh);
    if (tid == 0) {
        float N = (float)TWc * (float)TWc;
        float mT = s / N;
        s_mT = mT;
        s_tvar = q - N * mT * mT + EPSc;   // sum (t - mean)^2 + eps
    }
    __syncthreads();
    float mT = s_mT, tvar = s_tvar;

    if (tid < 441) {
        float corr = 0.f;
        for (int b = 0; b < ND; b++) corr += g_corr[b * 441 + tid];
        float ls  = g_ls[tid];
        float num = corr - mT * ls;
        float var = g_lq[tid] - ls * ls * (1.0f / ((float)TWc * (float)TWc)) + EPSc;
        var = fmaxf(var, 0.f);
        float ncc = num / sqrtf(tvar * var);
        if (isnan(ncc)) ncc = 0.f;
        s_ncc[tid] = ncc;
    }
    __syncthreads();

    // argmax with first-index tie-break (matches jnp.argmax)
    rv[tid]   = (tid < 441) ? s_ncc[tid] : -FLT_MAX;
    ridx[tid] = (tid < 441) ? tid : (1 << 20);
    __syncthreads();
    for (int off = 256; off > 0; off >>= 1) {
        if (tid < off) {
            float v2 = rv[tid + off]; int i2 = ridx[tid + off];
            if (v2 > rv[tid] || (v2 == rv[tid] && i2 < ridx[tid])) {
                rv[tid] = v2; ridx[tid] = i2;
            }
        }
        __syncthreads();
    }

    if (tid == 0) {
        int idx = ridx[0];
        int sx = idx / Sc, sy = idx % Sc;
        auto at = [&](int r, int c) {
            r = r < 0 ? 0 : (r > Sc - 1 ? Sc - 1 : r);
            c = c < 0 ? 0 : (c > Sc - 1 ? Sc - 1 : c);
            return logf(s_ncc[r * Sc + c]);
        };
        float l4  = 4.f * at(sx, sy);
        float lxm = at(sx - 1, sy), lxp = at(sx + 1, sy);
        float lym = at(sx, sy - 1), lyp = at(sx, sy + 1);
        float xs = -((float)sx - (float)MSc) - (lxm - lxp) / (2.f * lxm - l4 + 2.f * lxp);
        float ys = -((float)sy - (float)MSc) - (lym - lyp) / (2.f * lym - l4 + 2.f * lyp);
        g_xy[0] = xs; g_xy[1] = ys;
        if (out_size >= Hh * Ww + 2) {
            out[Hh * Ww]     = xs;
            out[Hh * Ww + 1] = ys;
        }
    }
}

// ---------------- F: bilinear shift + transposed store ----------------
__global__ void kF(const float* __restrict__ X, float* __restrict__ out) {
    __shared__ float tile[32][33];
    float xs = g_xy[0], ys = g_xy[1];
    int tx = threadIdx.x, ty = threadIdx.y;
    int r = blockIdx.y * 32 + ty;
    int c = blockIdx.x * 32 + tx;

    float rr = (float)r - xs, cc = (float)c - ys;
    float r0f = floorf(rr), c0f = floorf(cc);
    float wr = rr - r0f, wc = cc - c0f;
    int r0 = (int)r0f, c0 = (int)c0f;

    bool rv0 = (r0 >= 0 && r0 < Hh), rv1 = (r0 + 1 >= 0 && r0 + 1 < Hh);
    bool cv0 = (c0 >= 0 && c0 < Ww), cv1 = (c0 + 1 >= 0 && c0 + 1 < Ww);
    float v00 = 0.f, v01 = 0.f, v10 = 0.f, v11 = 0.f;
    if (rv0 && cv0) v00 = X[(size_t)r0 * Ww + c0];
    if (rv0 && cv1) v01 = X[(size_t)r0 * Ww + c0 + 1];
    if (rv1 && cv0) v10 = X[(size_t)(r0 + 1) * Ww + c0];
    if (rv1 && cv1) v11 = X[(size_t)(r0 + 1) * Ww + c0 + 1];

    float val = (1.f - wr) * (1.f - wc) * v00 + (1.f - wr) * wc * v01
              + wr * (1.f - wc) * v10 + wr * wc * v11;
    tile[ty][tx] = val;
    __syncthreads();

    int oc = blockIdx.x * 32 + ty;   // output column (of original image)
    int orr = blockIdx.y * 32 + tx;  // output row
    out[(size_t)oc * Hh + orr] = tile[tx][ty];   // flat = out.T.reshape(-1)
}

// ---------------- launch ----------------
extern "C" void kernel_launch(void* const* d_in, const int* in_sizes, int n_in,
                              void* d_out, int out_size) {
    const float* X    = (const float*)d_in[0];  // (1,1024,1024,1)
    const float* tmpl = (const float*)d_in[1];  // (1024,1024)
    float* out = (float*)d_out;

    kA<<<NA, 256>>>(tmpl);
    kB<<<4, 256>>>(X);
    kC<<<441, 128>>>();
    kD<<<ND, 192>>>(X, tmpl);
    kE<<<1, 512>>>(out, out_size);
    dim3 g(32, 32), blk(32, 32);
    kF<<<g, blk>>>(X, out);
}

// round 4
// speedup vs baseline: 1.2081x; 1.2081x over previous
#include <cuda_runtime.h>
#include <math.h>
#include <float.h>

#define Hh   1024
#define Ww   1024
#define CSc  62      // (1024-900)/2
#define OFFc 72      // MS + CS
#define TWc  880     // template window
#define Sc   21      // 2*MS+1
#define MSc  10
#define EPSc 1e-8f

#define NA  220      // kernel A blocks
#define ND2 484      // kernel D blocks (22 x 22 tiles of 40x40)

// ---------------- scratch (no allocation allowed) ----------------
__device__ float g_ta[NA], g_tq[NA];          // template partial sums / sumsq
__device__ float g_part[20 * 900];            // 45-row chunk partial sums
__device__ float g_partq[20 * 900];
__device__ float g_colx[21 * 900];            // column sliding sums of Xc
__device__ float g_colq[21 * 900];
__device__ float g_ls[441], g_lq[441];        // window sums / sumsq per lag
__device__ float g_corr[441 * ND2];           // lag-major correlation partials
__device__ float g_sum[441];                  // reduced correlation
__device__ float g_xy[2];                     // xs, ys

// ---------------- helpers ----------------
__device__ __forceinline__ void blockReduce2(float& s, float& q, float* sh) {
    int lane = threadIdx.x & 31, w = threadIdx.x >> 5;
    for (int o = 16; o > 0; o >>= 1) {
        s += __shfl_down_sync(0xffffffffu, s, o);
        q += __shfl_down_sync(0xffffffffu, q, o);
    }
    if (lane == 0) { sh[w] = s; sh[32 + w] = q; }
    __syncthreads();
    int nw = (blockDim.x + 31) >> 5;
    if (w == 0) {
        s = (lane < nw) ? sh[lane] : 0.f;
        q = (lane < nw) ? sh[32 + lane] : 0.f;
        for (int o = 16; o > 0; o >>= 1) {
            s += __shfl_down_sync(0xffffffffu, s, o);
            q += __shfl_down_sync(0xffffffffu, q, o);
        }
    }
}

// ---------------- A: template sum / sumsq over [72:952]^2 ----------------
__global__ void kA(const float* __restrict__ T) {
    __shared__ float sh[64];
    int b = blockIdx.x, tid = threadIdx.x;
    float s = 0.f, q = 0.f;
    for (int rr = 0; rr < 4; rr++) {
        const float* row = T + (size_t)(OFFc + b * 4 + rr) * Ww + OFFc;
        for (int v = tid; v < TWc; v += 256) {
            float t = row[v]; s += t; q = fmaf(t, t, q);
        }
    }
    blockReduce2(s, q, sh);
    if (tid == 0) { g_ta[b] = s; g_tq[b] = q; }
}

// ---------------- B1: per-column 45-row chunk partial sums ---------------
__global__ void kB1(const float* __restrict__ X) {
    int c = blockIdx.x * 128 + threadIdx.x;
    if (c >= 900) return;
    int r0 = blockIdx.y * 45;
    const float* p = X + (size_t)(CSc + r0) * Ww + CSc + c;
    float s = 0.f, q = 0.f;
#pragma unroll 5
    for (int r = 0; r < 45; r++) { float v = p[(size_t)r * Ww]; s += v; q = fmaf(v, v, q); }
    g_part[blockIdx.y * 900 + c] = s;
    g_partq[blockIdx.y * 900 + c] = q;
}

// ---------------- B2: total - head - tail  -> 21 sliding column sums -----
__global__ void kB2(const float* __restrict__ X) {
    int c = blockIdx.x * 256 + threadIdx.x;
    if (c >= 900) return;
    float s = 0.f, q = 0.f;
#pragma unroll
    for (int k = 0; k < 20; k++) { s += g_part[k * 900 + c]; q += g_partq[k * 900 + c]; }
    const float* p = X + (size_t)CSc * Ww + CSc + c;
    float ts = 0.f, tq = 0.f;
#pragma unroll
    for (int k = 0; k < 20; k++) {
        float w = p[(size_t)(880 + k) * Ww]; ts += w; tq = fmaf(w, w, tq);
    }
    float hp = 0.f, hq = 0.f;
#pragma unroll
    for (int i = 0; i < 21; i++) {
        g_colx[i * 900 + c] = s - hp - ts;
        g_colq[i * 900 + c] = q - hq - tq;
        if (i < 20) {
            float v = p[(size_t)i * Ww];          hp += v; hq = fmaf(v, v, hq);
            float w = p[(size_t)(880 + i) * Ww];  ts -= w; tq -= w * w;
        }
    }
}

// ---------------- C: 880-wide row sums of colwin -> ls, lsq per lag -------
__global__ void kC() {
    __shared__ float sh[64];
    int b = blockIdx.x;                // b = i*21 + j
    int i = b / 21, j = b % 21;
    int tid = threadIdx.x;
    float s = 0.f, q = 0.f;
    const float* px = g_colx + i * 900 + j;
    const float* pq = g_colq + i * 900 + j;
    for (int t = tid; t < TWc; t += 128) { s += px[t]; q += pq[t]; }
    blockReduce2(s, q, sh);
    if (tid == 0) { g_ls[b] = s; g_lq[b] = q; }
}

// ---------------- D: raw correlation, 40x40 tiles, register blocked ------
__global__ void __launch_bounds__(192) kD(const float* __restrict__ X,
                                          const float* __restrict__ T) {
    __shared__ float Xs[60 * 65];    // pitch 65 (== 1 mod 32): conflict-free
    __shared__ float Ts[40 * 41];    // pitch 41 (== 9 mod 32)
    int b = blockIdx.x;
    int bi = b / 22, bj = b % 22;    // 22 x 22 tiles of 40 x 40
    int bu0 = bi * 40, bv0 = bj * 40;
    int tid = threadIdx.x;

    const float* xg = X + (size_t)(CSc + bu0) * Ww + (CSc + bv0);
    for (int k = tid; k < 60 * 60; k += 192) {
        int ur = k / 60, uc = k - ur * 60;
        Xs[ur * 65 + uc] = xg[(size_t)ur * Ww + uc];
    }
    const float* tg = T + (size_t)(OFFc + bu0) * Ww + (OFFc + bv0);
    for (int k = tid; k < 40 * 40; k += 192) {
        int u = k >> 5, v = k & 31;  // 40x40 = 1600, pitch-friendly split
        // careful: 40 cols, use /40
        u = k / 40; v = k - u * 40;
        Ts[u * 41 + v] = tg[(size_t)u * Ww + v];
    }
    __syncthreads();

    if (tid < 168) {
        int i = tid >> 3;            // 0..20 row lag
        int r = tid & 7;             // reduction slice

        float acc[21];
#pragma unroll
        for (int j = 0; j < 21; j++) acc[j] = 0.f;

        for (int uu = 0; uu < 5; uu++) {     // rows r, r+8, ..., r+32
            int urow = r + uu * 8;
            const float* ts = Ts + urow * 41;
            const float* xs = Xs + (i + urow) * 65;
#pragma unroll
            for (int ch = 0; ch < 2; ch++) { // two 16-wide chunks
                float xw[36];
#pragma unroll
                for (int m = 0; m < 36; m++) xw[m] = xs[ch * 16 + m];
#pragma unroll
                for (int dv = 0; dv < 16; dv++) {
                    float t = ts[ch * 16 + dv];
#pragma unroll
                    for (int j = 0; j < 21; j++)
                        acc[j] = fmaf(t, xw[dv + j], acc[j]);
                }
            }
            {                                 // final 8-wide chunk (cols 32..39)
                float xw[28];
#pragma unroll
                for (int m = 0; m < 28; m++) xw[m] = xs[32 + m];
#pragma unroll
                for (int dv = 0; dv < 8; dv++) {
                    float t = ts[32 + dv];
#pragma unroll
                    for (int j = 0; j < 21; j++)
                        acc[j] = fmaf(t, xw[dv + j], acc[j]);
                }
            }
        }

#pragma unroll
        for (int j = 0; j < 21; j++) {
            float v = acc[j];
            v += __shfl_down_sync(0xffffffffu, v, 4, 8);
            v += __shfl_down_sync(0xffffffffu, v, 2, 8);
            v += __shfl_down_sync(0xffffffffu, v, 1, 8);
            if (r == 0)
                g_corr[(i * 21 + j) * ND2 + b] = v;   // lag-major for kE0
        }
    }
}

// ---------------- E0: reduce per-lag partials ----------------------------
__global__ void kE0() {
    __shared__ float sh[64];
    int lag = blockIdx.x, tid = threadIdx.x;
    float s = 0.f, dummy = 0.f;
    const float* p = g_corr + (size_t)lag * ND2;
    for (int k = tid; k < ND2; k += 128) s += p[k];
    blockReduce2(s, dummy, sh);
    if (tid == 0) g_sum[lag] = s;
}

// ---------------- E: NCC, argmax, subpixel ----------------
__global__ void __launch_bounds__(512) kE(float* __restrict__ out, int out_size) {
    __shared__ float sh[64];
    __shared__ float s_mT, s_tvar;
    __shared__ float s_ncc[441];
    __shared__ float rv[512];
    __shared__ int   ridx[512];
    int tid = threadIdx.x;

    // template stats
    float s = (tid < NA) ? g_ta[tid] : 0.f;
    float q = (tid < NA) ? g_tq[tid] : 0.f;
    blockReduce2(s, q, sh);
    if (tid == 0) {
        float N = (float)TWc * (float)TWc;
        float mT = s / N;
        s_mT = mT;
        s_tvar = q - N * mT * mT + EPSc;
    }
    __syncthreads();
    float mT = s_mT, tvar = s_tvar;

    if (tid < 441) {
        float corr = g_sum[tid];
        float ls   = g_ls[tid];
        float num  = corr - mT * ls;
        float var  = g_lq[tid] - ls * ls * (1.0f / ((float)TWc * (float)TWc)) + EPSc;
        var = fmaxf(var, 0.f);
        float ncc = num / sqrtf(tvar * var);
        if (isnan(ncc)) ncc = 0.f;
        s_ncc[tid] = ncc;
    }
    __syncthreads();

    rv[tid]   = (tid < 441) ? s_ncc[tid] : -FLT_MAX;
    ridx[tid] = (tid < 441) ? tid : (1 << 20);
    __syncthreads();
    for (int off = 256; off > 0; off >>= 1) {
        if (tid < off) {
            float v2 = rv[tid + off]; int i2 = ridx[tid + off];
            if (v2 > rv[tid] || (v2 == rv[tid] && i2 < ridx[tid])) {
                rv[tid] = v2; ridx[tid] = i2;
            }
        }
        __syncthreads();
    }

    if (tid == 0) {
        int idx = ridx[0];
        int sx = idx / Sc, sy = idx % Sc;
        auto at = [&](int r, int c) {
            r = r < 0 ? 0 : (r > Sc - 1 ? Sc - 1 : r);
            c = c < 0 ? 0 : (c > Sc - 1 ? Sc - 1 : c);
            return logf(s_ncc[r * Sc + c]);
        };
        float l4  = 4.f * at(sx, sy);
        float lxm = at(sx - 1, sy), lxp = at(sx + 1, sy);
        float lym = at(sx, sy - 1), lyp = at(sx, sy + 1);
        float xs = -((float)sx - (float)MSc) - (lxm - lxp) / (2.f * lxm - l4 + 2.f * lxp);
        float ys = -((float)sy - (float)MSc) - (lym - lyp) / (2.f * lym - l4 + 2.f * lyp);
        g_xy[0] = xs; g_xy[1] = ys;
        if (out_size >= Hh * Ww + 2) {
            out[Hh * Ww]     = xs;
            out[Hh * Ww + 1] = ys;
        }
    }
}

// ---------------- F: bilinear shift + transposed store ----------------
__global__ void kF(const float* __restrict__ X, float* __restrict__ out) {
    __shared__ float tile[32][33];
    float xs = g_xy[0], ys = g_xy[1];
    int tx = threadIdx.x, ty = threadIdx.y;
    int r = blockIdx.y * 32 + ty;
    int c = blockIdx.x * 32 + tx;

    float rr = (float)r - xs, cc = (float)c - ys;
    float r0f = floorf(rr), c0f = floorf(cc);
    float wr = rr - r0f, wc = cc - c0f;
    int r0 = (int)r0f, c0 = (int)c0f;

    bool rv0 = (r0 >= 0 && r0 < Hh), rv1 = (r0 + 1 >= 0 && r0 + 1 < Hh);
    bool cv0 = (c0 >= 0 && c0 < Ww), cv1 = (c0 + 1 >= 0 && c0 + 1 < Ww);
    float v00 = 0.f, v01 = 0.f, v10 = 0.f, v11 = 0.f;
    if (rv0 && cv0) v00 = X[(size_t)r0 * Ww + c0];
    if (rv0 && cv1) v01 = X[(size_t)r0 * Ww + c0 + 1];
    if (rv1 && cv0) v10 = X[(size_t)(r0 + 1) * Ww + c0];
    if (rv1 && cv1) v11 = X[(size_t)(r0 + 1) * Ww + c0 + 1];

    float val = (1.f - wr) * (1.f - wc) * v00 + (1.f - wr) * wc * v01
              + wr * (1.f - wc) * v10 + wr * wc * v11;
    tile[ty][tx] = val;
    __syncthreads();

    out[(size_t)(blockIdx.x * 32 + ty) * Hh + (blockIdx.y * 32 + tx)] = tile[tx][ty];
}

// ---------------- launch ----------------
extern "C" void kernel_launch(void* const* d_in, const int* in_sizes, int n_in,
                              void* d_out, int out_size) {
    const float* X    = (const float*)d_in[0];  // (1,1024,1024,1)
    const float* tmpl = (const float*)d_in[1];  // (1024,1024)
    float* out = (float*)d_out;

    static cudaStream_t s1;
    static cudaEvent_t evFork, evJoin;
    static int inited = 0, ok = 0;
    if (!inited) {
        inited = 1;
        ok = (cudaStreamCreateWithFlags(&s1, cudaStreamNonBlocking) == cudaSuccess) &&
             (cudaEventCreateWithFlags(&evFork, cudaEventDisableTiming) == cudaSuccess) &&
             (cudaEventCreateWithFlags(&evJoin, cudaEventDisableTiming) == cudaSuccess);
    }

    dim3 gB1(8, 20);
    dim3 gF(32, 32), bF(32, 32);

    if (ok) {
        cudaEventRecord(evFork, 0);
        cudaStreamWaitEvent(s1, evFork, 0);
        kA<<<NA, 256, 0, s1>>>(tmpl);
        kB1<<<gB1, 128, 0, s1>>>(X);
        kB2<<<4, 256, 0, s1>>>(X);
        kC<<<441, 128, 0, s1>>>();
        cudaEventRecord(evJoin, s1);

        kD<<<ND2, 192>>>(X, tmpl);
        kE0<<<441, 128>>>();
        cudaStreamWaitEvent(0, evJoin, 0);
        kE<<<1, 512>>>(out, out_size);
        kF<<<gF, bF>>>(X, out);
    } else {
        kA<<<NA, 256>>>(tmpl);
        kB1<<<gB1, 128>>>(X);
        kB2<<<4, 256>>>(X);
        kC<<<441, 128>>>();
        kD<<<ND2, 192>>>(X, tmpl);
        kE0<<<441, 128>>>();
        kE<<<1, 512>>>(out, out_size);
        kF<<<gF, bF>>>(X, out);
    }
}